// round 14
// baseline (speedup 1.0000x reference)
#include <cuda_runtime.h>
#include <cuda_fp16.h>

#define N_NODES 100000
#define E_EDGES 3200000
#define F 64
#define F4 16
#define STRIDE 96   // bucket capacity; deg ~ Poisson(32), 96 = 11-sigma margin
#define XPAD 36     // floats per staged X row (32 data + 4 pad: bank-conflict-free)

typedef unsigned long long u64;

// 8 halves = 16B — one lane's slice of an fp16 feature row (row = 8 slices).
struct alignas(16) H8 { __half2 h[4]; };

// Scratch (allocation-free rule: __device__ globals; zero-initialized at load)
__device__ H8    g_hs[N_NODES * 8];       // fp16 messages
__device__ float g_a1[N_NODES * F];       // fp32 relu output of layer 1
__device__ float g_dinv[N_NODES];
__device__ int   g_deg[N_NODES];          // per-call snapshot of in-degree
__device__ int   g_cnt[N_NODES];          // ALWAYS zero on entry (reset in k_post)
__device__ int   g_csr[N_NODES * STRIDE]; // bucketed adjacency (src ids by dst)

// ---- packed fp32x2 helpers (sm_103a) ----
__device__ __forceinline__ u64 fma2(u64 a, u64 b, u64 c) {
    u64 d;
    asm("fma.rn.f32x2 %0, %1, %2, %3;" : "=l"(d) : "l"(a), "l"(b), "l"(c));
    return d;
}
__device__ __forceinline__ u64 add2(u64 a, u64 b) {
    u64 d;
    asm("add.rn.f32x2 %0, %1, %2;" : "=l"(d) : "l"(a), "l"(b));
    return d;
}
__device__ __forceinline__ u64 bcast2(float x) {
    u64 p;
    asm("mov.b64 %0, {%1, %1};" : "=l"(p) : "f"(x));
    return p;
}
__device__ __forceinline__ u64 pack2(float lo, float hi) {
    u64 p;
    asm("mov.b64 %0, {%1, %2};" : "=l"(p) : "f"(lo), "f"(hi));
    return p;
}
__device__ __forceinline__ void unpack2(u64 p, float& lo, float& hi) {
    asm("mov.b64 {%0, %1}, %2;" : "=f"(lo), "=f"(hi) : "l"(p));
}
__device__ __forceinline__ u64 h2f2(__half2 h) {
    float2 f = __half22float2(h);
    return pack2(f.x, f.y);
}

// Bucketed CSR fill: one pass produces adjacency + degrees. 2 edges/thread.
__global__ __launch_bounds__(256)
void k_fillb(const int* __restrict__ src, const int* __restrict__ dst) {
    int e = (blockIdx.x * blockDim.x + threadIdx.x) * 2;
    if (e >= E_EDGES) return;
    int d0 = __ldg(&dst[e]);
    int d1 = __ldg(&dst[e + 1]);
    int s0 = __ldg(&src[e]);
    int s1 = __ldg(&src[e + 1]);
    int p0 = atomicAdd(&g_cnt[d0], 1);
    if (p0 < STRIDE) g_csr[d0 * STRIDE + p0] = s0;
    int p1 = atomicAdd(&g_cnt[d1], 1);
    if (p1 < STRIDE) g_csr[d1 * STRIDE + p1] = s1;
}

// Post pass (after gemm1 raw + fillb): per-slice scale g_hs by dinv[row],
// lane 0 of each 8-lane group writes dinv/deg and resets cnt.
__global__ __launch_bounds__(256)
void k_post() {
    int idx = blockIdx.x * blockDim.x + threadIdx.x;
    if (idx >= N_NODES * 8) return;
    int n = idx >> 3;
    int c = idx & 7;
    int cnt = g_cnt[n];
    float di = rsqrtf((float)(cnt + 1));
    H8 v = g_hs[idx];
#pragma unroll
    for (int j = 0; j < 4; j++) {
        float2 f = __half22float2(v.h[j]);
        v.h[j] = __floats2half2_rn(f.x * di, f.y * di);
    }
    g_hs[idx] = v;
    if (c == 0) {
        g_dinv[n] = di;
        g_deg[n]  = cnt;
        g_cnt[n]  = 0;   // reset for next call
    }
}

// GEMM with cp.async-staged X: 2-stage k-chunk pipeline (chunks of 32 k).
// 4-row x 8-col thread tiles, packed f32x2 FMA. Block = 128 rows.
// SCALE=false: store raw X@W (dinv applied later in k_post).
// SCALE=true:  apply dinv in epilogue (layer 2).
template<int K, bool SCALE>
__global__ __launch_bounds__(256, 3)
void k_gemmp(const float* __restrict__ X,
             const float* __restrict__ W) {
    extern __shared__ float sm[];
    float* Ws = sm;                       // K*64 floats
    float* Xs = sm + K * F;               // 2 stages x 128 rows x XPAD floats

    int tid  = threadIdx.x;
    int g    = tid >> 3;                  // 0..31 row slot
    int jseg = tid & 7;                   // 8-col segment
    int base = blockIdx.x * 128;

    // Stage W (synchronous; visible after first __syncthreads below)
    for (int t = tid; t < K * F4; t += 256)
        reinterpret_cast<float4*>(Ws)[t] = reinterpret_cast<const float4*>(W)[t];

    // async-copy one 128x32 X chunk into stage s
    auto issue = [&](int c, int s) {
#pragma unroll
        for (int i = 0; i < 4; i++) {
            int slot = tid + i * 256;          // 0..1023
            int row  = slot >> 3;              // 0..127
            int seg  = slot & 7;               // 16B segment within 128B
            int gr   = base + row;
            if (gr > N_NODES - 1) gr = N_NODES - 1;   // clamp (tail block)
            const float* gsrc = X + (size_t)gr * K + c * 32 + seg * 4;
            unsigned ds = (unsigned)__cvta_generic_to_shared(
                Xs + s * (128 * XPAD) + row * XPAD + seg * 4);
            asm volatile("cp.async.cg.shared.global [%0], [%1], 16;"
                         :: "r"(ds), "l"(gsrc));
        }
        asm volatile("cp.async.commit_group;");
    };

    const int NC = K / 32;
    issue(0, 0);

    u64 acc[4][4];
    u64 zz = bcast2(0.f);
#pragma unroll
    for (int i = 0; i < 4; i++)
#pragma unroll
        for (int j = 0; j < 4; j++) acc[i][j] = zz;

    for (int c = 0; c < NC; c++) {
        asm volatile("cp.async.wait_group 0;");
        __syncthreads();                       // chunk c ready; all warps past c-1
        if (c + 1 < NC) issue(c + 1, (c + 1) & 1);   // overlaps compute below
        const float* Xc = Xs + (c & 1) * (128 * XPAD);
        const float* Wc = Ws + c * 32 * F;
#pragma unroll
        for (int k4 = 0; k4 < 8; k4++) {
            float4 xv[4];
#pragma unroll
            for (int i = 0; i < 4; i++)
                xv[i] = *reinterpret_cast<const float4*>(
                    Xc + (i * 32 + g) * XPAD + k4 * 4);
#pragma unroll
            for (int kk = 0; kk < 4; kk++) {
                const ulonglong2* wp = reinterpret_cast<const ulonglong2*>(
                    Wc + (k4 * 4 + kk) * F + jseg * 8);
                ulonglong2 wa = wp[0];
                ulonglong2 wb = wp[1];
#pragma unroll
                for (int i = 0; i < 4; i++) {
                    float xk = (kk == 0) ? xv[i].x : (kk == 1) ? xv[i].y
                             : (kk == 2) ? xv[i].z : xv[i].w;
                    u64 bx = bcast2(xk);
                    acc[i][0] = fma2(bx, wa.x, acc[i][0]);
                    acc[i][1] = fma2(bx, wa.y, acc[i][1]);
                    acc[i][2] = fma2(bx, wb.x, acc[i][2]);
                    acc[i][3] = fma2(bx, wb.y, acc[i][3]);
                }
            }
        }
    }

#pragma unroll
    for (int i = 0; i < 4; i++) {
        int r = base + i * 32 + g;
        if (r >= N_NODES) continue;
        float s = SCALE ? g_dinv[r] : 1.0f;
        H8 v;
#pragma unroll
        for (int j = 0; j < 4; j++) {
            float lo, hi;
            unpack2(acc[i][j], lo, hi);
            v.h[j] = __floats2half2_rn(lo * s, hi * s);
        }
        g_hs[r * 8 + jseg] = v;
    }
}

// Bucketed gather-aggregate over fp16 messages, packed f32x2 accumulation.
// Full 8-edge batches run unconditionally; <8 remainder in a guarded tail.
// out[n] = (relu?)( dinv[n] * (hs[n] + sum_e hs[src_e]) + bias )
template<bool RELU>
__global__ __launch_bounds__(512)
void k_aggregate(const float* __restrict__ bias,
                 float4* __restrict__ outv) {
    int tid = threadIdx.x;
    int c   = tid & 7;
    int n   = blockIdx.x * 64 + (tid >> 3);
    if (n >= N_NODES) return;

    int end  = g_deg[n];
    int full = end & ~7;
    const int* adj = g_csr + n * STRIDE;

    u64 acc[4];
    {   // self-loop message
        H8 v = g_hs[n * 8 + c];
#pragma unroll
        for (int j = 0; j < 4; j++) acc[j] = h2f2(v.h[j]);
    }

    for (int j0 = 0; j0 < full; j0 += 8) {
#pragma unroll
        for (int k = 0; k < 8; k++) {
            int s = __ldg(&adj[j0 + k]);   // uniform per 8-lane group
            H8 v = g_hs[s * 8 + c];
#pragma unroll
            for (int j = 0; j < 4; j++)
                acc[j] = add2(acc[j], h2f2(v.h[j]));
        }
    }
    for (int j0 = full; j0 < end; j0++) {
        int s = __ldg(&adj[j0]);
        H8 v = g_hs[s * 8 + c];
#pragma unroll
        for (int j = 0; j < 4; j++)
            acc[j] = add2(acc[j], h2f2(v.h[j]));
    }

    float d = g_dinv[n];
    const float4* bb = reinterpret_cast<const float4*>(bias) + c * 2;
    float4 b0 = bb[0], b1 = bb[1];
    float a0, a1x, a2, a3, a4, a5, a6, a7;
    unpack2(acc[0], a0, a1x);
    unpack2(acc[1], a2, a3);
    unpack2(acc[2], a4, a5);
    unpack2(acc[3], a6, a7);
    float4 r0, r1;
    r0.x = fmaf(d, a0, b0.x);  r0.y = fmaf(d, a1x, b0.y);
    r0.z = fmaf(d, a2, b0.z);  r0.w = fmaf(d, a3, b0.w);
    r1.x = fmaf(d, a4, b1.x);  r1.y = fmaf(d, a5, b1.y);
    r1.z = fmaf(d, a6, b1.z);  r1.w = fmaf(d, a7, b1.w);
    if (RELU) {
        r0.x = fmaxf(r0.x, 0.f); r0.y = fmaxf(r0.y, 0.f);
        r0.z = fmaxf(r0.z, 0.f); r0.w = fmaxf(r0.w, 0.f);
        r1.x = fmaxf(r1.x, 0.f); r1.y = fmaxf(r1.y, 0.f);
        r1.z = fmaxf(r1.z, 0.f); r1.w = fmaxf(r1.w, 0.f);
    }
    outv[n * 16 + c * 2]     = r0;
    outv[n * 16 + c * 2 + 1] = r1;
}

extern "C" void kernel_launch(void* const* d_in, const int* in_sizes, int n_in,
                              void* d_out, int out_size) {
    const float* x   = (const float*)d_in[0];
    const int*   src = (const int*)d_in[1];
    const int*   dst = (const int*)d_in[1] + E_EDGES;
    const float* W1  = (const float*)d_in[2];
    const float* b1  = (const float*)d_in[3];
    const float* W2  = (const float*)d_in[4];
    const float* b2  = (const float*)d_in[5];
    float* out = (float*)d_out;

    float* a1 = nullptr;
    cudaGetSymbolAddress((void**)&a1, g_a1);

    // smem: W (K*64*4B) + 2 stages of 128 rows x XPAD floats
    const int SMEM1 = 128 * F * 4 + 2 * 128 * XPAD * 4;   // 69632
    const int SMEM2 =  64 * F * 4 + 2 * 128 * XPAD * 4;   // 53248

    // One-time resources (no device memory). Same enqueued work every call.
    static cudaStream_t s_side = nullptr;
    static cudaEvent_t  s_fork = nullptr, s_join = nullptr;
    if (!s_side) {
        cudaStreamCreateWithFlags(&s_side, cudaStreamNonBlocking);
        cudaEventCreateWithFlags(&s_fork, cudaEventDisableTiming);
        cudaEventCreateWithFlags(&s_join, cudaEventDisableTiming);
        cudaFuncSetAttribute(k_gemmp<128, false>,
                             cudaFuncAttributeMaxDynamicSharedMemorySize, SMEM1);
        cudaFuncSetAttribute(k_gemmp<64, true>,
                             cudaFuncAttributeMaxDynamicSharedMemorySize, SMEM2);
    }

    const int TB = 256;
    const int nb_fill  = (E_EDGES / 2 + TB - 1) / TB;
    const int nb_post  = (N_NODES * 8 + TB - 1) / TB;
    const int nb_gemm  = (N_NODES + 127) / 128;
    const int nb_agg   = (N_NODES + 63) / 64;

    // Fork: layer-1 GEMM (raw, no dinv) runs concurrently with CSR fill.
    cudaEventRecord(s_fork, 0);
    cudaStreamWaitEvent(s_side, s_fork, 0);
    k_gemmp<128, false><<<nb_gemm, 256, SMEM1, s_side>>>(x, W1);  // hs1 raw
    cudaEventRecord(s_join, s_side);

    k_fillb<<<nb_fill, TB>>>(src, dst);                 // adjacency + counts

    cudaStreamWaitEvent(0, s_join, 0);                  // join side stream

    // dinv + in-place hs scale + deg snapshot + cnt reset
    k_post<<<nb_post, TB>>>();

    // aggregate layer 1 (profiled)  a1 = relu(...) -> g_a1
    k_aggregate<true><<<nb_agg, 512>>>(b1, (float4*)a1);

    // layer-2 GEMM (dinv in epilogue)  hs2 -> g_hs
    k_gemmp<64, true><<<nb_gemm, 256, SMEM2>>>(a1, W2);

    // aggregate layer 2 -> d_out
    k_aggregate<false><<<nb_agg, 512>>>(b2, (float4*)out);
}

// round 15
// speedup vs baseline: 1.0060x; 1.0060x over previous
#include <cuda_runtime.h>
#include <cuda_fp16.h>

#define N_NODES 100000
#define E_EDGES 3200000
#define F 64
#define F4 16
#define STRIDE 96   // bucket capacity; deg ~ Poisson(32), 96 = 11-sigma margin

typedef unsigned long long u64;

// 8 halves = 16B — one lane's slice of an fp16 feature row (row = 8 slices).
struct alignas(16) H8 { __half2 h[4]; };

// Scratch (allocation-free rule: __device__ globals; zero-initialized at load)
__device__ H8    g_hs[N_NODES * 8];       // fp16 messages
__device__ float g_a1[N_NODES * F];       // fp32 relu output of layer 1
__device__ float g_dinv[N_NODES];
__device__ int   g_deg[N_NODES];          // per-call snapshot of in-degree
__device__ int   g_cnt[N_NODES];          // ALWAYS zero on entry (reset in k_post)
__device__ int   g_csr[N_NODES * STRIDE]; // bucketed adjacency (src ids by dst)

// ---- packed fp32x2 helpers (sm_103a) ----
__device__ __forceinline__ u64 fma2(u64 a, u64 b, u64 c) {
    u64 d;
    asm("fma.rn.f32x2 %0, %1, %2, %3;" : "=l"(d) : "l"(a), "l"(b), "l"(c));
    return d;
}
__device__ __forceinline__ u64 add2(u64 a, u64 b) {
    u64 d;
    asm("add.rn.f32x2 %0, %1, %2;" : "=l"(d) : "l"(a), "l"(b));
    return d;
}
__device__ __forceinline__ u64 bcast2(float x) {
    u64 p;
    asm("mov.b64 %0, {%1, %1};" : "=l"(p) : "f"(x));
    return p;
}
__device__ __forceinline__ u64 pack2(float lo, float hi) {
    u64 p;
    asm("mov.b64 %0, {%1, %2};" : "=l"(p) : "f"(lo), "f"(hi));
    return p;
}
__device__ __forceinline__ void unpack2(u64 p, float& lo, float& hi) {
    asm("mov.b64 {%0, %1}, %2;" : "=f"(lo), "=f"(hi) : "l"(p));
}
__device__ __forceinline__ u64 h2f2(__half2 h) {
    float2 f = __half22float2(h);
    return pack2(f.x, f.y);
}

// Bucketed CSR fill: one pass produces adjacency + degrees. 2 edges/thread.
__global__ __launch_bounds__(256)
void k_fillb(const int* __restrict__ src, const int* __restrict__ dst) {
    int e = (blockIdx.x * blockDim.x + threadIdx.x) * 2;
    if (e >= E_EDGES) return;
    int d0 = __ldg(&dst[e]);
    int d1 = __ldg(&dst[e + 1]);
    int s0 = __ldg(&src[e]);
    int s1 = __ldg(&src[e + 1]);
    int p0 = atomicAdd(&g_cnt[d0], 1);
    if (p0 < STRIDE) g_csr[d0 * STRIDE + p0] = s0;
    int p1 = atomicAdd(&g_cnt[d1], 1);
    if (p1 < STRIDE) g_csr[d1 * STRIDE + p1] = s1;
}

// Post pass (after gemm1 raw + fillb): per-slice scale g_hs by dinv[row],
// lane 0 of each 8-lane group writes dinv/deg and resets cnt.
__global__ __launch_bounds__(256)
void k_post() {
    int idx = blockIdx.x * blockDim.x + threadIdx.x;
    if (idx >= N_NODES * 8) return;
    int n = idx >> 3;
    int c = idx & 7;
    int cnt = g_cnt[n];
    float di = rsqrtf((float)(cnt + 1));
    H8 v = g_hs[idx];
#pragma unroll
    for (int j = 0; j < 4; j++) {
        float2 f = __half22float2(v.h[j]);
        v.h[j] = __floats2half2_rn(f.x * di, f.y * di);
    }
    g_hs[idx] = v;
    __syncwarp();
    if (c == 0) {
        g_dinv[n] = di;
        g_deg[n]  = cnt;
        g_cnt[n]  = 0;   // reset for next call
    }
}

// GEMM, 4-row x 8-col thread tiles with packed f32x2 FMA.
// Register diet: int float4-offsets instead of pointer arrays, and a hard
// 64-reg cap (__launch_bounds__(256,4)) -> 4 blocks/SM, ~50% occupancy.
// SCALE=false: store raw X@W (dinv applied later in k_post).
// SCALE=true:  apply dinv in epilogue (layer 2, dinv already valid).
template<int K, bool SCALE>
__global__ __launch_bounds__(256, 4)
void k_gemmh(const float* __restrict__ X,
             const float* __restrict__ W) {
    __shared__ float Ws[K * F];
    for (int t = threadIdx.x; t < K * F4; t += 256)
        reinterpret_cast<float4*>(Ws)[t] = reinterpret_cast<const float4*>(W)[t];
    __syncthreads();

    int g    = threadIdx.x >> 3;     // 0..31 row slot
    int jseg = threadIdx.x & 7;      // 8-col segment
    int base = blockIdx.x * 128;

    const float4* X4 = reinterpret_cast<const float4*>(X);
    int off[4];                      // float4 offset of each row (int: fits)
#pragma unroll
    for (int i = 0; i < 4; i++) {
        int r = base + i * 32 + g;
        if (r > N_NODES - 1) r = N_NODES - 1;   // clamp (tail block)
        off[i] = r * (K / 4);
    }

    u64 acc[4][4];
    u64 zz = bcast2(0.f);
#pragma unroll
    for (int i = 0; i < 4; i++)
#pragma unroll
        for (int j = 0; j < 4; j++) acc[i][j] = zz;

    for (int k4 = 0; k4 < K / 4; k4++) {
        float4 xv[4];
#pragma unroll
        for (int i = 0; i < 4; i++) xv[i] = __ldg(&X4[off[i] + k4]);
#pragma unroll
        for (int kk = 0; kk < 4; kk++) {
            const ulonglong2* wp = reinterpret_cast<const ulonglong2*>(
                Ws + (k4 * 4 + kk) * F + jseg * 8);
            ulonglong2 wa = wp[0];
            ulonglong2 wb = wp[1];
#pragma unroll
            for (int i = 0; i < 4; i++) {
                float xk = (kk == 0) ? xv[i].x : (kk == 1) ? xv[i].y
                         : (kk == 2) ? xv[i].z : xv[i].w;
                u64 bx = bcast2(xk);
                acc[i][0] = fma2(bx, wa.x, acc[i][0]);
                acc[i][1] = fma2(bx, wa.y, acc[i][1]);
                acc[i][2] = fma2(bx, wb.x, acc[i][2]);
                acc[i][3] = fma2(bx, wb.y, acc[i][3]);
            }
        }
    }

#pragma unroll
    for (int i = 0; i < 4; i++) {
        int r = base + i * 32 + g;
        if (r >= N_NODES) continue;
        float s = SCALE ? g_dinv[r] : 1.0f;
        H8 v;
#pragma unroll
        for (int j = 0; j < 4; j++) {
            float lo, hi;
            unpack2(acc[i][j], lo, hi);
            v.h[j] = __floats2half2_rn(lo * s, hi * s);
        }
        g_hs[r * 8 + jseg] = v;
    }
}

// Bucketed gather-aggregate over fp16 messages, packed f32x2 accumulation.
// Full 8-edge batches run UNCONDITIONALLY; <8 remainder in a guarded tail.
// out[n] = (relu?)( dinv[n] * (hs[n] + sum_e hs[src_e]) + bias )
template<bool RELU>
__global__ __launch_bounds__(512)
void k_aggregate(const float* __restrict__ bias,
                 float4* __restrict__ outv) {
    int tid = threadIdx.x;
    int c   = tid & 7;
    int n   = blockIdx.x * 64 + (tid >> 3);
    if (n >= N_NODES) return;

    int end  = g_deg[n];
    int full = end & ~7;
    const int* adj = g_csr + n * STRIDE;

    u64 acc[4];
    {   // self-loop message
        H8 v = g_hs[n * 8 + c];
#pragma unroll
        for (int j = 0; j < 4; j++) acc[j] = h2f2(v.h[j]);
    }

    for (int j0 = 0; j0 < full; j0 += 8) {
#pragma unroll
        for (int k = 0; k < 8; k++) {
            int s = __ldg(&adj[j0 + k]);   // uniform per 8-lane group
            H8 v = g_hs[s * 8 + c];
#pragma unroll
            for (int j = 0; j < 4; j++)
                acc[j] = add2(acc[j], h2f2(v.h[j]));
        }
    }
    for (int j0 = full; j0 < end; j0++) {
        int s = __ldg(&adj[j0]);
        H8 v = g_hs[s * 8 + c];
#pragma unroll
        for (int j = 0; j < 4; j++)
            acc[j] = add2(acc[j], h2f2(v.h[j]));
    }

    float d = g_dinv[n];
    const float4* bb = reinterpret_cast<const float4*>(bias) + c * 2;
    float4 b0 = bb[0], b1 = bb[1];
    float a0, a1x, a2, a3, a4, a5, a6, a7;
    unpack2(acc[0], a0, a1x);
    unpack2(acc[1], a2, a3);
    unpack2(acc[2], a4, a5);
    unpack2(acc[3], a6, a7);
    float4 r0, r1;
    r0.x = fmaf(d, a0, b0.x);  r0.y = fmaf(d, a1x, b0.y);
    r0.z = fmaf(d, a2, b0.z);  r0.w = fmaf(d, a3, b0.w);
    r1.x = fmaf(d, a4, b1.x);  r1.y = fmaf(d, a5, b1.y);
    r1.z = fmaf(d, a6, b1.z);  r1.w = fmaf(d, a7, b1.w);
    if (RELU) {
        r0.x = fmaxf(r0.x, 0.f); r0.y = fmaxf(r0.y, 0.f);
        r0.z = fmaxf(r0.z, 0.f); r0.w = fmaxf(r0.w, 0.f);
        r1.x = fmaxf(r1.x, 0.f); r1.y = fmaxf(r1.y, 0.f);
        r1.z = fmaxf(r1.z, 0.f); r1.w = fmaxf(r1.w, 0.f);
    }
    outv[n * 16 + c * 2]     = r0;
    outv[n * 16 + c * 2 + 1] = r1;
}

extern "C" void kernel_launch(void* const* d_in, const int* in_sizes, int n_in,
                              void* d_out, int out_size) {
    const float* x   = (const float*)d_in[0];
    const int*   src = (const int*)d_in[1];
    const int*   dst = (const int*)d_in[1] + E_EDGES;
    const float* W1  = (const float*)d_in[2];
    const float* b1  = (const float*)d_in[3];
    const float* W2  = (const float*)d_in[4];
    const float* b2  = (const float*)d_in[5];
    float* out = (float*)d_out;

    float* a1 = nullptr;
    cudaGetSymbolAddress((void**)&a1, g_a1);

    // One-time resources (no device memory). Same enqueued work every call.
    static cudaStream_t s_side = nullptr;
    static cudaEvent_t  s_fork = nullptr, s_join = nullptr;
    if (!s_side) {
        cudaStreamCreateWithFlags(&s_side, cudaStreamNonBlocking);
        cudaEventCreateWithFlags(&s_fork, cudaEventDisableTiming);
        cudaEventCreateWithFlags(&s_join, cudaEventDisableTiming);
    }

    const int TB = 256;
    const int nb_fill  = (E_EDGES / 2 + TB - 1) / TB;
    const int nb_post  = (N_NODES * 8 + TB - 1) / TB;
    const int nb_gemm  = (N_NODES + 127) / 128;
    const int nb_agg   = (N_NODES + 63) / 64;

    // Fork: layer-1 GEMM (raw, no dinv) runs concurrently with CSR fill.
    cudaEventRecord(s_fork, 0);
    cudaStreamWaitEvent(s_side, s_fork, 0);
    k_gemmh<128, false><<<nb_gemm, 256, 0, s_side>>>(x, W1);   // hs1 raw -> g_hs
    cudaEventRecord(s_join, s_side);

    k_fillb<<<nb_fill, TB>>>(src, dst);                        // adjacency + counts

    cudaStreamWaitEvent(0, s_join, 0);                         // join side stream

    // dinv + in-place hs scale + deg snapshot + cnt reset
    k_post<<<nb_post, TB>>>();

    // aggregate layer 1 (profiled)  a1 = relu(...) -> g_a1
    k_aggregate<true><<<nb_agg, 512>>>(b1, (float4*)a1);

    // layer-2 GEMM (dinv in epilogue)  hs2 -> g_hs
    k_gemmh<64, true><<<nb_gemm, 256>>>(a1, W2);

    // aggregate layer 2 -> d_out
    k_aggregate<false><<<nb_agg, 512>>>(b2, (float4*)out);
}

// round 16
// speedup vs baseline: 1.3926x; 1.3844x over previous
#include <cuda_runtime.h>
#include <cuda_fp16.h>

#define N_NODES 100000
#define E_EDGES 3200000
#define F 64
#define STRIDE 96   // bucket capacity; deg ~ Poisson(32), 96 = 11-sigma margin

typedef unsigned long long u64;
typedef unsigned int u32;

// 8 halves = 16B — one lane's slice of an fp16 feature row (row = 8 slices).
struct alignas(16) H8 { __half2 h[4]; };

// Scratch (allocation-free rule: __device__ globals; zero-initialized at load)
__device__ H8    g_hs[N_NODES * 8];       // fp16 messages (64 halves per node)
__device__ float g_a1[N_NODES * F];       // fp32 relu output of layer 1
__device__ float g_dinv[N_NODES];
__device__ int   g_deg[N_NODES];          // per-call snapshot of in-degree
__device__ int   g_cnt[N_NODES];          // ALWAYS zero on entry (reset in k_post)
__device__ int   g_csr[N_NODES * STRIDE]; // bucketed adjacency (src ids by dst)

// ---- packed fp32x2 helpers (sm_103a) ----
__device__ __forceinline__ u64 add2(u64 a, u64 b) {
    u64 d;
    asm("add.rn.f32x2 %0, %1, %2;" : "=l"(d) : "l"(a), "l"(b));
    return d;
}
__device__ __forceinline__ u64 pack2(float lo, float hi) {
    u64 p;
    asm("mov.b64 %0, {%1, %2};" : "=l"(p) : "f"(lo), "f"(hi));
    return p;
}
__device__ __forceinline__ void unpack2(u64 p, float& lo, float& hi) {
    asm("mov.b64 {%0, %1}, %2;" : "=f"(lo), "=f"(hi) : "l"(p));
}
__device__ __forceinline__ u64 h2f2(__half2 h) {
    float2 f = __half22float2(h);
    return pack2(f.x, f.y);
}
__device__ __forceinline__ u32 f2h2(float lo, float hi) {
    __half2 h = __floats2half2_rn(lo, hi);
    return *reinterpret_cast<u32*>(&h);
}

// m16n8k16 row.col f16xf16 -> f32 accumulate (HMMA on sm_103a)
__device__ __forceinline__ void mma16816(float* d,
                                         u32 a0, u32 a1, u32 a2, u32 a3,
                                         u32 b0, u32 b1) {
    asm volatile(
        "mma.sync.aligned.m16n8k16.row.col.f32.f16.f16.f32 "
        "{%0,%1,%2,%3}, {%4,%5,%6,%7}, {%8,%9}, {%0,%1,%2,%3};"
        : "+f"(d[0]), "+f"(d[1]), "+f"(d[2]), "+f"(d[3])
        : "r"(a0), "r"(a1), "r"(a2), "r"(a3), "r"(b0), "r"(b1));
}

// Bucketed CSR fill: one pass produces adjacency + degrees. 2 edges/thread.
__global__ __launch_bounds__(256)
void k_fillb(const int* __restrict__ src, const int* __restrict__ dst) {
    int e = (blockIdx.x * blockDim.x + threadIdx.x) * 2;
    if (e >= E_EDGES) return;
    int d0 = __ldg(&dst[e]);
    int d1 = __ldg(&dst[e + 1]);
    int s0 = __ldg(&src[e]);
    int s1 = __ldg(&src[e + 1]);
    int p0 = atomicAdd(&g_cnt[d0], 1);
    if (p0 < STRIDE) g_csr[d0 * STRIDE + p0] = s0;
    int p1 = atomicAdd(&g_cnt[d1], 1);
    if (p1 < STRIDE) g_csr[d1 * STRIDE + p1] = s1;
}

// Post pass (after gemm1 raw + fillb): per-slice scale g_hs by dinv[row],
// lane 0 of each 8-lane group writes dinv/deg and resets cnt.
__global__ __launch_bounds__(256)
void k_post() {
    int idx = blockIdx.x * blockDim.x + threadIdx.x;
    if (idx >= N_NODES * 8) return;
    int n = idx >> 3;
    int c = idx & 7;
    int cnt = g_cnt[n];
    float di = rsqrtf((float)(cnt + 1));
    H8 v = g_hs[idx];
#pragma unroll
    for (int j = 0; j < 4; j++) {
        float2 f = __half22float2(v.h[j]);
        v.h[j] = __floats2half2_rn(f.x * di, f.y * di);
    }
    g_hs[idx] = v;
    __syncwarp();
    if (c == 0) {
        g_dinv[n] = di;
        g_deg[n]  = cnt;
        g_cnt[n]  = 0;   // reset for next call
    }
}

// Tensor-core GEMM: hs = (X[M,K] @ W[K,64]) [* dinv], output fp16 to g_hs.
// Block = 256 threads = 8 warps; warp w owns rows [base+16w, base+16w+16).
// W is converted once per block to fp16, transposed to Wsh[n][k] with a
// padded row (PADK) making B-fragment LDS.32 bank-conflict-free.
// Fragment mapping (PTX m16n8k16.row.col): grp=lane>>2, tig=lane&3.
//   A: a0=(r=grp,     k=2tig,2tig+1)  a1=(r=grp+8, same)
//      a2=(r=grp,     k=8+2tig,+1)    a3=(r=grp+8, same)
//   B: b0=(k=2tig,2tig+1, n=grp)      b1=(k=8+2tig,+1, n=grp)
//   D: d0,d1=(r=grp, n=2tig,2tig+1)   d2,d3=(r=grp+8, same)
template<int K, bool SCALE>
__global__ __launch_bounds__(256)
void k_gemmt(const float* __restrict__ X, const float* __restrict__ W) {
    constexpr int PADK = K + 8;
    __shared__ __half Wsh[64 * PADK];

    int tid = threadIdx.x;
    // Convert W[k][n] (k-major fp32) -> Wsh[n][k] (fp16, padded rows)
    for (int idx = tid; idx < K * 64; idx += 256) {
        int k = idx >> 6;
        int n = idx & 63;
        Wsh[n * PADK + k] = __float2half_rn(W[idx]);
    }
    __syncthreads();

    int warp = tid >> 5;
    int lane = tid & 31;
    int grp  = lane >> 2;
    int tig  = lane & 3;
    int rowbase = blockIdx.x * 128 + warp * 16;

    int r0 = rowbase + grp;        // A rows owned by this lane
    int r1 = r0 + 8;
    int r0c = min(r0, N_NODES - 1);
    int r1c = min(r1, N_NODES - 1);
    const float* x0 = X + (size_t)r0c * K;
    const float* x1 = X + (size_t)r1c * K;

    float d[8][4] = {};            // 8 n-tiles x 4 accum

#pragma unroll
    for (int ks = 0; ks < K / 16; ks++) {
        int kb = ks * 16;
        float2 f;
        f = *reinterpret_cast<const float2*>(x0 + kb + 2 * tig);
        u32 a0 = f2h2(f.x, f.y);
        f = *reinterpret_cast<const float2*>(x1 + kb + 2 * tig);
        u32 a1 = f2h2(f.x, f.y);
        f = *reinterpret_cast<const float2*>(x0 + kb + 8 + 2 * tig);
        u32 a2 = f2h2(f.x, f.y);
        f = *reinterpret_cast<const float2*>(x1 + kb + 8 + 2 * tig);
        u32 a3 = f2h2(f.x, f.y);
#pragma unroll
        for (int nt = 0; nt < 8; nt++) {
            int n = nt * 8 + grp;
            const u32* bp = reinterpret_cast<const u32*>(Wsh + n * PADK + kb);
            u32 b0 = bp[tig];        // halves kb+2tig, kb+2tig+1
            u32 b1 = bp[4 + tig];    // halves kb+8+2tig, +1
            mma16816(d[nt], a0, a1, a2, a3, b0, b1);
        }
    }

    // Epilogue: scale (optional) + fp16 pack + half2 stores into g_hs
    __half2* out = reinterpret_cast<__half2*>(g_hs);   // 32 half2 per node row
    float s0 = SCALE ? g_dinv[r0c] : 1.0f;
    float s1 = SCALE ? g_dinv[r1c] : 1.0f;
    if (r0 < N_NODES) {
#pragma unroll
        for (int nt = 0; nt < 8; nt++)
            out[r0 * 32 + nt * 4 + tig] = __floats2half2_rn(d[nt][0] * s0,
                                                            d[nt][1] * s0);
    }
    if (r1 < N_NODES) {
#pragma unroll
        for (int nt = 0; nt < 8; nt++)
            out[r1 * 32 + nt * 4 + tig] = __floats2half2_rn(d[nt][2] * s1,
                                                            d[nt][3] * s1);
    }
}

// Bucketed gather-aggregate over fp16 messages, packed f32x2 accumulation.
// Full 8-edge batches run UNCONDITIONALLY; <8 remainder in a guarded tail.
// out[n] = (relu?)( dinv[n] * (hs[n] + sum_e hs[src_e]) + bias )
template<bool RELU>
__global__ __launch_bounds__(512)
void k_aggregate(const float* __restrict__ bias,
                 float4* __restrict__ outv) {
    int tid = threadIdx.x;
    int c   = tid & 7;
    int n   = blockIdx.x * 64 + (tid >> 3);
    if (n >= N_NODES) return;

    int end  = g_deg[n];
    int full = end & ~7;
    const int* adj = g_csr + n * STRIDE;

    u64 acc[4];
    {   // self-loop message
        H8 v = g_hs[n * 8 + c];
#pragma unroll
        for (int j = 0; j < 4; j++) acc[j] = h2f2(v.h[j]);
    }

    for (int j0 = 0; j0 < full; j0 += 8) {
#pragma unroll
        for (int k = 0; k < 8; k++) {
            int s = __ldg(&adj[j0 + k]);   // uniform per 8-lane group
            H8 v = g_hs[s * 8 + c];
#pragma unroll
            for (int j = 0; j < 4; j++)
                acc[j] = add2(acc[j], h2f2(v.h[j]));
        }
    }
    for (int j0 = full; j0 < end; j0++) {
        int s = __ldg(&adj[j0]);
        H8 v = g_hs[s * 8 + c];
#pragma unroll
        for (int j = 0; j < 4; j++)
            acc[j] = add2(acc[j], h2f2(v.h[j]));
    }

    float d = g_dinv[n];
    const float4* bb = reinterpret_cast<const float4*>(bias) + c * 2;
    float4 b0 = bb[0], b1 = bb[1];
    float a0, a1x, a2, a3, a4, a5, a6, a7;
    unpack2(acc[0], a0, a1x);
    unpack2(acc[1], a2, a3);
    unpack2(acc[2], a4, a5);
    unpack2(acc[3], a6, a7);
    float4 r0, r1;
    r0.x = fmaf(d, a0, b0.x);  r0.y = fmaf(d, a1x, b0.y);
    r0.z = fmaf(d, a2, b0.z);  r0.w = fmaf(d, a3, b0.w);
    r1.x = fmaf(d, a4, b1.x);  r1.y = fmaf(d, a5, b1.y);
    r1.z = fmaf(d, a6, b1.z);  r1.w = fmaf(d, a7, b1.w);
    if (RELU) {
        r0.x = fmaxf(r0.x, 0.f); r0.y = fmaxf(r0.y, 0.f);
        r0.z = fmaxf(r0.z, 0.f); r0.w = fmaxf(r0.w, 0.f);
        r1.x = fmaxf(r1.x, 0.f); r1.y = fmaxf(r1.y, 0.f);
        r1.z = fmaxf(r1.z, 0.f); r1.w = fmaxf(r1.w, 0.f);
    }
    outv[n * 16 + c * 2]     = r0;
    outv[n * 16 + c * 2 + 1] = r1;
}

extern "C" void kernel_launch(void* const* d_in, const int* in_sizes, int n_in,
                              void* d_out, int out_size) {
    const float* x   = (const float*)d_in[0];
    const int*   src = (const int*)d_in[1];
    const int*   dst = (const int*)d_in[1] + E_EDGES;
    const float* W1  = (const float*)d_in[2];
    const float* b1  = (const float*)d_in[3];
    const float* W2  = (const float*)d_in[4];
    const float* b2  = (const float*)d_in[5];
    float* out = (float*)d_out;

    float* a1 = nullptr;
    cudaGetSymbolAddress((void**)&a1, g_a1);

    // One-time resources (no device memory). Same enqueued work every call.
    static cudaStream_t s_side = nullptr;
    static cudaEvent_t  s_fork = nullptr, s_join = nullptr;
    if (!s_side) {
        cudaStreamCreateWithFlags(&s_side, cudaStreamNonBlocking);
        cudaEventCreateWithFlags(&s_fork, cudaEventDisableTiming);
        cudaEventCreateWithFlags(&s_join, cudaEventDisableTiming);
    }

    const int TB = 256;
    const int nb_fill = (E_EDGES / 2 + TB - 1) / TB;
    const int nb_post = (N_NODES * 8 + TB - 1) / TB;
    const int nb_gemm = (N_NODES + 127) / 128;
    const int nb_agg  = (N_NODES + 63) / 64;

    // Fork: layer-1 GEMM (raw, no dinv) runs concurrently with CSR fill.
    cudaEventRecord(s_fork, 0);
    cudaStreamWaitEvent(s_side, s_fork, 0);
    k_gemmt<128, false><<<nb_gemm, 256, 0, s_side>>>(x, W1);   // hs1 raw -> g_hs
    cudaEventRecord(s_join, s_side);

    k_fillb<<<nb_fill, TB>>>(src, dst);                        // adjacency + counts

    cudaStreamWaitEvent(0, s_join, 0);                         // join side stream

    // dinv + in-place hs scale + deg snapshot + cnt reset
    k_post<<<nb_post, TB>>>();

    // aggregate layer 1  a1 = relu(...) -> g_a1
    k_aggregate<true><<<nb_agg, 512>>>(b1, (float4*)a1);

    // layer-2 GEMM (dinv in epilogue)  hs2 -> g_hs
    k_gemmt<64, true><<<nb_gemm, 256>>>(a1, W2);

    // aggregate layer 2 -> d_out
    k_aggregate<false><<<nb_agg, 512>>>(b2, (float4*)out);
}